// round 1
// baseline (speedup 1.0000x reference)
#include <cuda_runtime.h>

#define BATCH 65536
#define KPOS  6
#define KNEG  30
#define NGR   12
#define DIM   50
#define D2    25   // float2 per row

__global__ void ft_zero_kernel(float* out) { out[0] = 0.0f; }

__global__ __launch_bounds__(256, 8) void fasttext_loss_kernel(
    const int*   __restrict__ input_labels,
    const int*   __restrict__ pos_labels,
    const int*   __restrict__ neg_labels,
    const int*   __restrict__ trigram_idx,
    const int*   __restrict__ ngram_mask,
    const float* __restrict__ center_W,
    const float* __restrict__ background_W,
    const float* __restrict__ trigram_W,
    float*       __restrict__ out)
{
    const unsigned FULL = 0xffffffffu;
    const int lane = threadIdx.x & 31;
    const int wid  = threadIdx.x >> 5;
    const int gw   = blockIdx.x * 8 + wid;
    const int nw   = gridDim.x * 8;
    const bool act = (lane < D2);

    float loss = 0.0f;

    for (int b = gw; b < BATCH; b += nw) {
        // ---- build context vector m = center + sum(masked trigrams) ----
        float m0 = 0.0f, m1 = 0.0f;
        {
            const float2* r = reinterpret_cast<const float2*>(
                center_W + (size_t)input_labels[b] * DIM);
            if (act) { float2 v = __ldg(r + lane); m0 = v.x; m1 = v.y; }
        }
        #pragma unroll
        for (int n = 0; n < NGR; ++n) {
            // warp-uniform branch: skip masked-out ngrams (halves trigram traffic)
            if (ngram_mask[b * NGR + n] != 0) {
                const float2* r = reinterpret_cast<const float2*>(
                    trigram_W + (size_t)trigram_idx[b * NGR + n] * DIM);
                if (act) { float2 v = __ldg(r + lane); m0 += v.x; m1 += v.y; }
            }
        }

        // ---- 36 dot products, pair-reduced; softplus via log of product ----
        float prod = 1.0f;

        // positives: softplus(-s) -> factor (1 + exp(-s))
        #pragma unroll
        for (int k = 0; k < KPOS; k += 2) {
            int l0 = pos_labels[b * KPOS + k];
            int l1 = pos_labels[b * KPOS + k + 1];
            float p0 = 0.0f, p1 = 0.0f;
            if (act) {
                float2 e0 = __ldg(reinterpret_cast<const float2*>(
                    background_W + (size_t)l0 * DIM) + lane);
                float2 e1 = __ldg(reinterpret_cast<const float2*>(
                    background_W + (size_t)l1 * DIM) + lane);
                p0 = m0 * e0.x + m1 * e0.y;
                p1 = m0 * e1.x + m1 * e1.y;
            }
            // 2 dots in 5 shuffles: lanes 0-15 end with s0, lanes 16-31 with s1
            float keep = (lane < 16) ? p0 : p1;
            float send = (lane < 16) ? p1 : p0;
            keep += __shfl_xor_sync(FULL, send, 16);
            keep += __shfl_xor_sync(FULL, keep, 8);
            keep += __shfl_xor_sync(FULL, keep, 4);
            keep += __shfl_xor_sync(FULL, keep, 2);
            keep += __shfl_xor_sync(FULL, keep, 1);
            // one warp-wide expf covers both labels (different value per half)
            prod *= (1.0f + __expf(-keep));
        }

        // negatives: softplus(s) -> factor (1 + exp(s))
        #pragma unroll
        for (int k = 0; k < KNEG; k += 2) {
            int l0 = neg_labels[b * KNEG + k];
            int l1 = neg_labels[b * KNEG + k + 1];
            float p0 = 0.0f, p1 = 0.0f;
            if (act) {
                float2 e0 = __ldg(reinterpret_cast<const float2*>(
                    background_W + (size_t)l0 * DIM) + lane);
                float2 e1 = __ldg(reinterpret_cast<const float2*>(
                    background_W + (size_t)l1 * DIM) + lane);
                p0 = m0 * e0.x + m1 * e0.y;
                p1 = m0 * e1.x + m1 * e1.y;
            }
            float keep = (lane < 16) ? p0 : p1;
            float send = (lane < 16) ? p1 : p0;
            keep += __shfl_xor_sync(FULL, send, 16);
            keep += __shfl_xor_sync(FULL, keep, 8);
            keep += __shfl_xor_sync(FULL, keep, 4);
            keep += __shfl_xor_sync(FULL, keep, 2);
            keep += __shfl_xor_sync(FULL, keep, 1);
            prod *= (1.0f + __expf(keep));
        }

        // lanes 0-15 hold product over even labels, 16-31 over odd labels
        loss += __logf(prod);
    }

    // combine the two half-warp partial sums (every lane then holds warp total)
    loss += __shfl_xor_sync(FULL, loss, 16);

    __shared__ float ws[8];
    if (lane == 0) ws[wid] = loss;
    __syncthreads();
    if (threadIdx.x == 0) {
        float s = 0.0f;
        #pragma unroll
        for (int i = 0; i < 8; ++i) s += ws[i];
        atomicAdd(out, s);
    }
}

extern "C" void kernel_launch(void* const* d_in, const int* in_sizes, int n_in,
                              void* d_out, int out_size) {
    const int*   input_labels = (const int*)  d_in[0];
    const int*   pos_labels   = (const int*)  d_in[1];
    const int*   neg_labels   = (const int*)  d_in[2];
    const int*   trigram_idx  = (const int*)  d_in[3];
    const int*   ngram_mask   = (const int*)  d_in[4];
    const float* center_W     = (const float*)d_in[5];
    const float* background_W = (const float*)d_in[6];
    const float* trigram_W    = (const float*)d_in[7];
    float* out = (float*)d_out;

    ft_zero_kernel<<<1, 1>>>(out);
    fasttext_loss_kernel<<<1184, 256>>>(
        input_labels, pos_labels, neg_labels, trigram_idx, ngram_mask,
        center_W, background_W, trigram_W, out);
}